// round 6
// baseline (speedup 1.0000x reference)
#include <cuda_runtime.h>

// out[n, c, k] = sum_h (1 - tanh^2(pre[n,h])) * W1[k,h] * W2[h,c]
// pre[n,h] = b1[h] + pos[n,0]*W1[0,h] + pos[n,1]*W1[1,h] + pos[n,2]*W1[2,h]
//
// Reformulated as out[n, m] = sum_h g[n,h] * M[h,m],  m = c*3+k,
// M[h,m] = W2[h,c]*W1[k,h] built in shared memory per 64-h chunk.
// Inner accumulate uses packed fma.rn.f32x2 (2 FMAs/inst on sm_103a).

#define NN   50000
#define HH   256
#define CC   32
#define MOUT 96      // C*3 outputs per node
#define CH   64      // h-chunk held in smem (64*96*4B = 24.5 KB)
#define TPB  128

__global__ __launch_bounds__(TPB)
void grad_kernel(const float* __restrict__ pos,
                 const float* __restrict__ W1,   // [3, H] row-major
                 const float* __restrict__ b1,   // [H]
                 const float* __restrict__ W2,   // [H, C] row-major
                 float* __restrict__ out)        // [N, C, 3]
{
    __shared__ float  Ms[CH * MOUT];   // M[h][m] for current chunk
    __shared__ float4 ws4[CH];         // {b1, W1[0], W1[1], W1[2]} per h

    const int tid = threadIdx.x;
    const int n   = blockIdx.x * TPB + tid;

    float px = 0.f, py = 0.f, pz = 0.f;
    if (n < NN) {
        px = pos[3 * n + 0];
        py = pos[3 * n + 1];
        pz = pos[3 * n + 2];
    }

    // 96 fp32 accumulators packed as 48 x b64 (f32x2)
    unsigned long long acc[48];
#pragma unroll
    for (int j = 0; j < 48; ++j) acc[j] = 0ull;

    for (int h0 = 0; h0 < HH; h0 += CH) {
        __syncthreads();   // protect smem reuse across chunks

        if (tid < CH) {
            int h = h0 + tid;
            ws4[tid] = make_float4(b1[h], W1[h], W1[HH + h], W1[2 * HH + h]);
        }
#pragma unroll
        for (int e = tid; e < CH * MOUT; e += TPB) {
            int h = e / MOUT;
            int m = e - h * MOUT;
            int c = m / 3;
            int k = m - 3 * c;
            Ms[e] = W2[(h0 + h) * CC + c] * W1[k * HH + (h0 + h)];
        }
        __syncthreads();

        if (n < NN) {
            for (int h = 0; h < CH; ++h) {
                // activation derivative g = 1 - tanh(pre)^2, overflow-safe:
                //   s = 2/(e^{2x}+1)  (t = 1-s),  g = s*(2-s)
                float4 w   = ws4[h];
                float  pre = fmaf(px, w.y, fmaf(py, w.z, fmaf(pz, w.w, w.x)));
                float  u   = __expf(pre + pre);        // inf for large pre -> s=0 -> g=0
                float  s   = __fdividef(2.0f, u + 1.0f);
                float  g   = s * (2.0f - s);

                unsigned long long g2;
                asm("mov.b64 %0, {%1, %1};" : "=l"(g2) : "f"(g));

                const ulonglong2* Mrow =
                    reinterpret_cast<const ulonglong2*>(&Ms[h * MOUT]);
#pragma unroll
                for (int j = 0; j < 24; ++j) {
                    ulonglong2 mv = Mrow[j];           // LDS.128, warp-broadcast
                    asm("fma.rn.f32x2 %0, %1, %2, %0;"
                        : "+l"(acc[2 * j])     : "l"(g2), "l"(mv.x));
                    asm("fma.rn.f32x2 %0, %1, %2, %0;"
                        : "+l"(acc[2 * j + 1]) : "l"(g2), "l"(mv.y));
                }
            }
        }
    }

    if (n < NN) {
        float4* out4 = reinterpret_cast<float4*>(out) + (size_t)n * (MOUT / 4);
#pragma unroll
        for (int j = 0; j < 24; ++j) {
            float4 o;
            asm("mov.b64 {%0, %1}, %2;" : "=f"(o.x), "=f"(o.y) : "l"(acc[2 * j]));
            asm("mov.b64 {%0, %1}, %2;" : "=f"(o.z), "=f"(o.w) : "l"(acc[2 * j + 1]));
            out4[j] = o;                               // STG.128
        }
    }
}

extern "C" void kernel_launch(void* const* d_in, const int* in_sizes, int n_in,
                              void* d_out, int out_size)
{
    const float* pos = (const float*)d_in[0];  // [N,3]
    const float* W1  = (const float*)d_in[1];  // [3,H]
    const float* b1  = (const float*)d_in[2];  // [H]
    const float* W2  = (const float*)d_in[3];  // [H,C]
    float* out = (float*)d_out;                // [N,C,3] fp32

    int grid = (NN + TPB - 1) / TPB;           // 391 CTAs, single wave
    grad_kernel<<<grid, TPB>>>(pos, W1, b1, W2, out);
}

// round 9
// speedup vs baseline: 1.0468x; 1.0468x over previous
#include <cuda_runtime.h>

// out[n, c, k] = sum_h g(pre[n,h]) * W1[k,h] * W2[h,c],  g = 1 - tanh^2
// pre[n,h] = b1[h] + pos[n]·W1[:,h]
//
// out[n, m] = sum_h g[n,h] * M[h,m],  m = c*3+k,  M[h,m] = W2[h,c]*W1[k,h].
// CTA: 64 nodes, 256 threads = 4 slices of 24 output columns per node.
// Per 64-h chunk: phase1 stages g[h][node] in smem (activation computed once),
// phase2 does the register-blocked accumulate with packed fma.rn.f32x2.

#define NN   50000
#define HH   256
#define CC   32
#define MOUT 96
#define CH   64     // h per chunk
#define NPC  64     // nodes per CTA
#define TPB  256
#define MSL  24     // output columns per slice (4 slices)

__global__ __launch_bounds__(TPB, 4)
void grad_kernel(const float* __restrict__ pos,
                 const float* __restrict__ W1,   // [3, H]
                 const float* __restrict__ b1,   // [H]
                 const float* __restrict__ W2,   // [H, C]
                 float* __restrict__ out)        // [N, C, 3]
{
    __shared__ float4 ws4[HH];                       // {b1, W1x, W1y, W1z} per h (4 KB)
    __shared__ float  pxs[NPC], pys[NPC], pzs[NPC];
    __shared__ __align__(16) float Ms[CH * MOUT];    // M chunk (24 KB)
    __shared__ float  gs[CH * NPC];                  // gs[h][node] (16 KB)

    const int tid  = threadIdx.x;
    const int blk  = blockIdx.x;
    const int node = tid >> 2;      // phase-2 node (0..63)
    const int slc  = tid & 3;       // phase-2 output slice
    const int n    = blk * NPC + node;

    // ---- one-time setup: activation weights + this CTA's positions ----
    if (tid < HH)  // TPB == HH
        ws4[tid] = make_float4(b1[tid], W1[tid], W1[HH + tid], W1[2 * HH + tid]);
    if (tid < 3 * NPC) {
        int gidx = blk * 3 * NPC + tid;                 // pos is [N,3] packed
        float v  = (gidx < 3 * NN) ? pos[gidx] : 0.f;
        int pn = tid / 3, comp = tid - 3 * pn;
        if      (comp == 0) pxs[pn] = v;
        else if (comp == 1) pys[pn] = v;
        else                pzs[pn] = v;
    }
    __syncthreads();

    // 24 fp32 accumulators as 12 packed b64
    unsigned long long acc[12];
#pragma unroll
    for (int j = 0; j < 12; ++j) acc[j] = 0ull;

    const int p1n  = tid & 63;      // phase-1 node
    const int p1hi = tid >> 6;      // phase-1 h sub-block (0..3)
    const float ppx = pxs[p1n], ppy = pys[p1n], ppz = pzs[p1n];

    for (int h0 = 0; h0 < HH; h0 += CH) {
        // build M chunk (global reads, L2-resident)
        for (int e = tid; e < CH * MOUT; e += TPB) {
            int h = e / MOUT;
            int m = e - h * MOUT;
            int c = m / 3;
            int k = m - 3 * c;
            Ms[e] = W2[(h0 + h) * CC + c] * W1[k * HH + (h0 + h)];
        }

        // phase 1: stage g for 64 h x 64 nodes (16 values per thread)
#pragma unroll 4
        for (int i = 0; i < 16; ++i) {
            int    h   = p1hi * 16 + i;
            float4 w   = ws4[h0 + h];                       // warp-uniform broadcast
            float  pre = fmaf(ppx, w.y, fmaf(ppy, w.z, fmaf(ppz, w.w, w.x)));
            // g = 1 - tanh^2 = s*(2-s), s = 2/(e^{2x}+1); overflow-safe
            float  u   = __expf(pre + pre);
            float  s   = __fdividef(2.0f, u + 1.0f);
            gs[h * NPC + p1n] = s * (2.0f - s);
        }
        __syncthreads();

        // phase 2: accumulate 24 outputs per thread
#pragma unroll 2
        for (int h = 0; h < CH; ++h) {
            float gv = gs[h * NPC + node];          // 8 words x 4-way broadcast
            unsigned long long g2;
            asm("mov.b64 %0, {%1, %1};" : "=l"(g2) : "f"(gv));

            const ulonglong2* Mrow =
                reinterpret_cast<const ulonglong2*>(&Ms[h * MOUT + slc * MSL]);
#pragma unroll
            for (int j = 0; j < 6; ++j) {
                ulonglong2 mv = Mrow[j];            // LDS.128, conflict-free
                asm("fma.rn.f32x2 %0, %1, %2, %0;"
                    : "+l"(acc[2 * j])     : "l"(g2), "l"(mv.x));
                asm("fma.rn.f32x2 %0, %1, %2, %0;"
                    : "+l"(acc[2 * j + 1]) : "l"(g2), "l"(mv.y));
            }
        }
        __syncthreads();            // protect Ms/gs before next chunk overwrites
    }

    if (n < NN) {
        float4* o4 = reinterpret_cast<float4*>(out) + (size_t)n * (MOUT / 4) + slc * (MSL / 4);
#pragma unroll
        for (int j = 0; j < 6; ++j) {
            float4 o;
            asm("mov.b64 {%0, %1}, %2;" : "=f"(o.x), "=f"(o.y) : "l"(acc[2 * j]));
            asm("mov.b64 {%0, %1}, %2;" : "=f"(o.z), "=f"(o.w) : "l"(acc[2 * j + 1]));
            o4[j] = o;                              // STG.128
        }
    }
}

extern "C" void kernel_launch(void* const* d_in, const int* in_sizes, int n_in,
                              void* d_out, int out_size)
{
    const float* pos = (const float*)d_in[0];  // [N,3]
    const float* W1  = (const float*)d_in[1];  // [3,H]
    const float* b1  = (const float*)d_in[2];  // [H]
    const float* W2  = (const float*)d_in[3];  // [H,C]
    float* out = (float*)d_out;                // [N,C,3] fp32

    int grid = (NN + NPC - 1) / NPC;           // 782 CTAs
    grad_kernel<<<grid, TPB>>>(pos, W1, b1, W2, out);
}

// round 11
// speedup vs baseline: 2.0872x; 1.9940x over previous
#include <cuda_runtime.h>

// out[n, c, k] = sum_h g(pre[n,h]) * W1[k,h] * W2[h,c],  g = 1 - tanh^2
// pre[n,h] = b1[h] + pos[n]·W1[:,h]
//
// out[n, m] = sum_h g[n,h] * M[h,m],  m = c*3+k,  M[h,m] = W2[h,c]*W1[k,h].
// CTA: 64 nodes, 128 threads. Thread = 4 nodes x 12 output cols (48 fp32 accs).
// Per h: 1 LDS.128 (g of 4 nodes) + 3 LDS.128 (12-col M slice) -> 24 FFMA2.

#define NN   50000
#define HH   256
#define CC   32
#define MOUT 96
#define CH   64     // h per chunk
#define NPC  64     // nodes per CTA
#define TPB  128
#define RN   4      // nodes per thread
#define MSL  12     // output columns per thread

__global__ __launch_bounds__(TPB, 4)
void grad_kernel(const float* __restrict__ pos,
                 const float* __restrict__ W1,   // [3, H]
                 const float* __restrict__ b1,   // [H]
                 const float* __restrict__ W2,   // [H, C]
                 float* __restrict__ out)        // [N, C, 3]
{
    __shared__ float4 ws4[HH];                       // {b1, W1x, W1y, W1z} (4 KB)
    __shared__ float  pxs[NPC], pys[NPC], pzs[NPC];
    __shared__ __align__(16) float Ms[CH * MOUT];    // M chunk (24 KB)
    __shared__ __align__(16) float gs[CH * NPC];     // g[h][node] (16 KB)

    const int tid = threadIdx.x;
    const int blk = blockIdx.x;
    const int slc = tid & 7;        // column slice (12 cols)
    const int ng  = tid >> 3;       // node group (4 nodes), 0..15
    const int n0  = blk * NPC + ng * RN;

    // ---- one-time setup ----
    for (int i = tid; i < HH; i += TPB)
        ws4[i] = make_float4(b1[i], W1[i], W1[HH + i], W1[2 * HH + i]);
    for (int i = tid; i < 3 * NPC; i += TPB) {
        int gidx = blk * 3 * NPC + i;                // pos is [N,3] packed
        float v  = (gidx < 3 * NN) ? pos[gidx] : 0.f;
        int pn = i / 3, comp = i - 3 * pn;
        if      (comp == 0) pxs[pn] = v;
        else if (comp == 1) pys[pn] = v;
        else                pzs[pn] = v;
    }
    __syncthreads();

    // 4 nodes x 12 cols accumulators as 4 x 6 packed b64
    unsigned long long acc[RN][6];
#pragma unroll
    for (int r = 0; r < RN; ++r)
#pragma unroll
        for (int j = 0; j < 6; ++j) acc[r][j] = 0ull;

    // phase-1 mapping: thread -> (node, 32-h half)
    const int p1n  = tid & 63;
    const int p1hi = tid >> 6;      // 0 or 1
    const float ppx = pxs[p1n], ppy = pys[p1n], ppz = pzs[p1n];

    // M-build mapping: thread (tid<96) owns output column m = tid
    const int mc = tid / 3;          // channel c
    const int mk = tid - 3 * mc;     // spatial k

    for (int h0 = 0; h0 < HH; h0 += CH) {
        // build M chunk: column-per-thread, div-free inner loop
        if (tid < MOUT) {
            const float* w2c = W2 + (size_t)h0 * CC + mc;   // stride CC per h
            const float* w1k = W1 + mk * HH + h0;
#pragma unroll 4
            for (int h = 0; h < CH; ++h)
                Ms[h * MOUT + tid] = w2c[h * CC] * w1k[h];
        }

        // phase 1: stage g for 64 h x 64 nodes (32 per thread)
#pragma unroll 4
        for (int i = 0; i < 32; ++i) {
            int    h   = p1hi * 32 + i;
            float4 w   = ws4[h0 + h];                       // warp-uniform
            float  pre = fmaf(ppx, w.y, fmaf(ppy, w.z, fmaf(ppz, w.w, w.x)));
            // g = 1 - tanh^2 = s*(2-s), s = 2/(e^{2x}+1); overflow-safe
            float  u   = __expf(pre + pre);
            float  s   = __fdividef(2.0f, u + 1.0f);
            gs[h * NPC + p1n] = s * (2.0f - s);
        }
        __syncthreads();

        // phase 2: 24 FFMA2 per h per thread
#pragma unroll 2
        for (int h = 0; h < CH; ++h) {
            // g for this thread's 4 nodes: one LDS.128, conflict-free
            float4 g4 = *reinterpret_cast<const float4*>(&gs[h * NPC + ng * RN]);
            unsigned long long g2[RN];
            asm("mov.b64 %0, {%1, %1};" : "=l"(g2[0]) : "f"(g4.x));
            asm("mov.b64 %0, {%1, %1};" : "=l"(g2[1]) : "f"(g4.y));
            asm("mov.b64 %0, {%1, %1};" : "=l"(g2[2]) : "f"(g4.z));
            asm("mov.b64 %0, {%1, %1};" : "=l"(g2[3]) : "f"(g4.w));

            // 12-col M slice: 3 LDS.128 = 6 packed b64, conflict-free
            const ulonglong2* Mrow =
                reinterpret_cast<const ulonglong2*>(&Ms[h * MOUT + slc * MSL]);
            ulonglong2 m0 = Mrow[0], m1 = Mrow[1], m2 = Mrow[2];

#pragma unroll
            for (int r = 0; r < RN; ++r) {
                asm("fma.rn.f32x2 %0, %1, %2, %0;" : "+l"(acc[r][0]) : "l"(g2[r]), "l"(m0.x));
                asm("fma.rn.f32x2 %0, %1, %2, %0;" : "+l"(acc[r][1]) : "l"(g2[r]), "l"(m0.y));
                asm("fma.rn.f32x2 %0, %1, %2, %0;" : "+l"(acc[r][2]) : "l"(g2[r]), "l"(m1.x));
                asm("fma.rn.f32x2 %0, %1, %2, %0;" : "+l"(acc[r][3]) : "l"(g2[r]), "l"(m1.y));
                asm("fma.rn.f32x2 %0, %1, %2, %0;" : "+l"(acc[r][4]) : "l"(g2[r]), "l"(m2.x));
                asm("fma.rn.f32x2 %0, %1, %2, %0;" : "+l"(acc[r][5]) : "l"(g2[r]), "l"(m2.y));
            }
        }
        __syncthreads();            // protect Ms/gs before next chunk
    }

    // store: 3 STG.128 per node (12 cols, 16B-aligned: slc*48B)
#pragma unroll
    for (int r = 0; r < RN; ++r) {
        int n = n0 + r;
        if (n < NN) {
            float4* o4 = reinterpret_cast<float4*>(out + (size_t)n * MOUT + slc * MSL);
#pragma unroll
            for (int j = 0; j < 3; ++j) {
                float4 o;
                asm("mov.b64 {%0, %1}, %2;" : "=f"(o.x), "=f"(o.y) : "l"(acc[r][2 * j]));
                asm("mov.b64 {%0, %1}, %2;" : "=f"(o.z), "=f"(o.w) : "l"(acc[r][2 * j + 1]));
                o4[j] = o;
            }
        }
    }
}

extern "C" void kernel_launch(void* const* d_in, const int* in_sizes, int n_in,
                              void* d_out, int out_size)
{
    const float* pos = (const float*)d_in[0];  // [N,3]
    const float* W1  = (const float*)d_in[1];  // [3,H]
    const float* b1  = (const float*)d_in[2];  // [H]
    const float* W2  = (const float*)d_in[3];  // [H,C]
    float* out = (float*)d_out;                // [N,C,3] fp32

    int grid = (NN + NPC - 1) / NPC;           // 782 CTAs
    grad_kernel<<<grid, TPB>>>(pos, W1, b1, W2, out);
}